// round 1
// baseline (speedup 1.0000x reference)
#include <cuda_runtime.h>

#define SEQ   8192
#define DKE   64
#define QT    128          // query rows per CTA (= blockDim)
#define KT    64           // keys per smem tile
#define CHUNK 1024         // keys per split-K chunk
#define NQT   (SEQ/QT)     // 64 query tiles
#define MAXC  (SEQ/CHUNK)  // 8 max chunks
#define CPT   (CHUNK/QT)   // 8 (q-tiles per chunk granularity)

// Split-K partial results (scratch: __device__ globals, no allocation)
__device__ float g_pout[MAXC][SEQ][DKE];  // unnormalized partial O
__device__ float g_pm[MAXC][SEQ];         // partial row max
__device__ float g_pl[MAXC][SEQ];         // partial row sum

__global__ __launch_bounds__(QT, 2)
void attn_phase1(const float* __restrict__ q,
                 const float* __restrict__ k,
                 const float* __restrict__ v) {
    const int m = blockIdx.y;          // query tile index
    const int c = blockIdx.x;          // chunk index
    if (c > m / CPT) return;           // n_chunks(m) = m/8 + 1

    __shared__ float ks[KT][DKE];
    __shared__ float vs[KT][DKE];

    const int tid = threadIdx.x;
    const int row = m * QT + tid;

    // q row -> registers (vectorized)
    float qr[DKE];
    const float4* qg = (const float4*)(q + (size_t)row * DKE);
    #pragma unroll
    for (int t = 0; t < DKE / 4; t++) {
        float4 x = qg[t];
        qr[4*t+0] = x.x; qr[4*t+1] = x.y; qr[4*t+2] = x.z; qr[4*t+3] = x.w;
    }

    float acc[DKE];
    #pragma unroll
    for (int d = 0; d < DKE; d++) acc[d] = 0.f;
    float mR = -1e30f;
    float lR = 0.f;

    const int kstart = c * CHUNK;
    const int kend   = min(kstart + CHUNK, (m + 1) * QT);  // causal limit for this q tile

    for (int kt = kstart; kt < kend; kt += KT) {
        __syncthreads();
        // cooperative K/V tile load (contiguous 16KB each, float4 coalesced)
        const float4* kg  = (const float4*)(k + (size_t)kt * DKE);
        const float4* vg  = (const float4*)(v + (size_t)kt * DKE);
        float4* ksl = (float4*)ks;
        float4* vsl = (float4*)vs;
        #pragma unroll
        for (int t = 0; t < (KT * DKE / 4) / QT; t++) {
            int i = tid + t * QT;
            ksl[i] = kg[i];
            vsl[i] = vg[i];
        }
        __syncthreads();

        // causal bound inside tile: keys j with kt + j <= row
        int jmax = row - kt + 1;
        if (jmax > KT) jmax = KT;

        #pragma unroll 2
        for (int j = 0; j < jmax; j++) {
            // dot(q_row, k_j): broadcast smem reads, 4 accumulator chains
            const float4* kr = (const float4*)ks[j];
            float a0 = 0.f, a1 = 0.f, a2 = 0.f, a3 = 0.f;
            #pragma unroll
            for (int t = 0; t < DKE / 4; t++) {
                float4 kv = kr[t];
                a0 = fmaf(qr[4*t+0], kv.x, a0);
                a1 = fmaf(qr[4*t+1], kv.y, a1);
                a2 = fmaf(qr[4*t+2], kv.z, a2);
                a3 = fmaf(qr[4*t+3], kv.w, a3);
            }
            float s = ((a0 + a1) + (a2 + a3)) * (1.0f / DKE);

            // online softmax with deferred rescale (rare branch)
            if (s > mR) {
                float cf = __expf(mR - s);   // first key: exp(-1e30-s)=0 zeroes state
                mR = s;
                lR *= cf;
                #pragma unroll
                for (int d = 0; d < DKE; d++) acc[d] *= cf;
            }
            float p = __expf(s - mR);
            lR += p;

            const float4* vr = (const float4*)vs[j];
            #pragma unroll
            for (int t = 0; t < DKE / 4; t++) {
                float4 vv = vr[t];
                acc[4*t+0] = fmaf(p, vv.x, acc[4*t+0]);
                acc[4*t+1] = fmaf(p, vv.y, acc[4*t+1]);
                acc[4*t+2] = fmaf(p, vv.z, acc[4*t+2]);
                acc[4*t+3] = fmaf(p, vv.w, acc[4*t+3]);
            }
        }
    }

    g_pm[c][row] = mR;
    g_pl[c][row] = lR;
    float4* po = (float4*)g_pout[c][row];
    #pragma unroll
    for (int t = 0; t < DKE / 4; t++)
        po[t] = make_float4(acc[4*t+0], acc[4*t+1], acc[4*t+2], acc[4*t+3]);
}

// Combine: one warp per row; lane handles dims (lane, lane+32). Coalesced.
__global__ void attn_phase2(float* __restrict__ out) {
    const int row  = blockIdx.x * 8 + (threadIdx.x >> 5);
    const int lane = threadIdx.x & 31;
    const int nch  = (row / QT) / CPT + 1;

    float gmax = -1e30f;
    #pragma unroll
    for (int c = 0; c < MAXC; c++)
        if (c < nch) gmax = fmaxf(gmax, g_pm[c][row]);

    float denom = 0.f, o0 = 0.f, o1 = 0.f;
    for (int c = 0; c < nch; c++) {
        float w = __expf(g_pm[c][row] - gmax);   // fully-masked partial: w -> 0
        denom = fmaf(w, g_pl[c][row], denom);
        o0 = fmaf(w, g_pout[c][row][lane],      o0);
        o1 = fmaf(w, g_pout[c][row][lane + 32], o1);
    }
    float inv = 1.0f / denom;
    out[(size_t)row * DKE + lane]      = o0 * inv;
    out[(size_t)row * DKE + lane + 32] = o1 * inv;
}

extern "C" void kernel_launch(void* const* d_in, const int* in_sizes, int n_in,
                              void* d_out, int out_size) {
    const float* q = (const float*)d_in[0];
    const float* k = (const float*)d_in[1];
    const float* v = (const float*)d_in[2];
    float* out = (float*)d_out;

    dim3 grid1(MAXC, NQT);             // 8 x 64; inactive (c,m) pairs exit fast
    attn_phase1<<<grid1, QT>>>(q, k, v);
    attn_phase2<<<SEQ / 8, 256>>>(out);
}

// round 2
// speedup vs baseline: 1.0743x; 1.0743x over previous
#include <cuda_runtime.h>

#define SEQ   8192
#define DKE   64
#define QT    128          // query rows per CTA (= blockDim)
#define KT    64           // keys per smem tile
#define CHUNK 1024         // keys per split-K chunk
#define NQT   (SEQ/QT)     // 64 query tiles
#define MAXC  (SEQ/CHUNK)  // 8 max chunks
#define CPT   (CHUNK/QT)   // 8

typedef unsigned long long u64t;

// Split-K partial results (scratch: __device__ globals, no allocation)
__device__ float g_pout[MAXC][SEQ][DKE];  // unnormalized partial O
__device__ float g_pm[MAXC][SEQ];         // partial row max
__device__ float g_pl[MAXC][SEQ];         // partial row sum

// ---- packed f32x2 helpers (sm_100+) ----
__device__ __forceinline__ u64t fma2(u64t a, u64t b, u64t c) {
    u64t d;
    asm("fma.rn.f32x2 %0, %1, %2, %3;" : "=l"(d) : "l"(a), "l"(b), "l"(c));
    return d;
}
__device__ __forceinline__ u64t mul2(u64t a, u64t b) {
    u64t d;
    asm("mul.rn.f32x2 %0, %1, %2;" : "=l"(d) : "l"(a), "l"(b));
    return d;
}
__device__ __forceinline__ u64t pack2(float lo, float hi) {
    u64t d;
    asm("mov.b64 %0, {%1, %2};" : "=l"(d) : "f"(lo), "f"(hi));
    return d;
}
__device__ __forceinline__ void unpack2(u64t a, float& lo, float& hi) {
    asm("mov.b64 {%0, %1}, %2;" : "=f"(lo), "=f"(hi) : "l"(a));
}

__global__ __launch_bounds__(QT, 2)
void attn_phase1(const float* __restrict__ q,
                 const float* __restrict__ k,
                 const float* __restrict__ v) {
    const int m = blockIdx.y;          // query tile index
    const int c = blockIdx.x;          // chunk index
    if (c > m / CPT) return;           // n_chunks(m) = m/8 + 1

    __shared__ float ks[KT][DKE];
    __shared__ float vs[KT][DKE];

    const int tid = threadIdx.x;
    const int row = m * QT + tid;

    // q row -> 32 packed f32x2 registers
    u64t qp[DKE / 2];
    {
        const ulonglong2* qg = (const ulonglong2*)(q + (size_t)row * DKE);
        #pragma unroll
        for (int t = 0; t < DKE / 4; t++) {
            ulonglong2 x = qg[t];
            qp[2 * t]     = x.x;
            qp[2 * t + 1] = x.y;
        }
    }

    u64t acc[DKE / 2];                 // 32 packed accumulators
    #pragma unroll
    for (int d = 0; d < DKE / 2; d++) acc[d] = 0ULL;   // (0.f, 0.f)
    float mR = -1e30f;
    float lR = 0.f;

    const int kstart = c * CHUNK;
    const int kend   = min(kstart + CHUNK, (m + 1) * QT);

    for (int kt = kstart; kt < kend; kt += KT) {
        __syncthreads();
        // cooperative K/V tile load (contiguous 16KB each, float4 coalesced)
        const float4* kg  = (const float4*)(k + (size_t)kt * DKE);
        const float4* vg  = (const float4*)(v + (size_t)kt * DKE);
        float4* ksl = (float4*)ks;
        float4* vsl = (float4*)vs;
        #pragma unroll
        for (int t = 0; t < (KT * DKE / 4) / QT; t++) {
            int i = tid + t * QT;
            ksl[i] = kg[i];
            vsl[i] = vg[i];
        }
        __syncthreads();

        // causal bound inside tile
        int jmax = row - kt + 1;
        if (jmax > KT) jmax = KT;

        #pragma unroll 2
        for (int j = 0; j < jmax; j++) {
            // ---- dot(q_row, k_j): packed pairs, 4 chains, broadcast LDS.128 ----
            const ulonglong2* kr = (const ulonglong2*)ks[j];
            u64t a0 = 0ULL, a1 = 0ULL, a2 = 0ULL, a3 = 0ULL;
            #pragma unroll
            for (int t = 0; t < DKE / 4; t++) {
                ulonglong2 kv = kr[t];
                if (t & 1) {
                    a2 = fma2(qp[2 * t],     kv.x, a2);
                    a3 = fma2(qp[2 * t + 1], kv.y, a3);
                } else {
                    a0 = fma2(qp[2 * t],     kv.x, a0);
                    a1 = fma2(qp[2 * t + 1], kv.y, a1);
                }
            }
            float x0, x1, x2, x3, x4, x5, x6, x7;
            unpack2(a0, x0, x1); unpack2(a1, x2, x3);
            unpack2(a2, x4, x5); unpack2(a3, x6, x7);
            float s = (((x0 + x1) + (x2 + x3)) + ((x4 + x5) + (x6 + x7)))
                      * (1.0f / DKE);

            // ---- online softmax, deferred rescale (rare branch) ----
            if (s > mR) {
                float cf = __expf(mR - s);   // first key: exp(-inf) = 0 zeroes state
                mR = s;
                lR *= cf;
                u64t cf2 = pack2(cf, cf);
                #pragma unroll
                for (int d = 0; d < DKE / 2; d++) acc[d] = mul2(acc[d], cf2);
            }
            float p = __expf(s - mR);
            lR += p;
            u64t pp = pack2(p, p);

            // ---- acc += p * v_j ----
            const ulonglong2* vr = (const ulonglong2*)vs[j];
            #pragma unroll
            for (int t = 0; t < DKE / 4; t++) {
                ulonglong2 vv = vr[t];
                acc[2 * t]     = fma2(pp, vv.x, acc[2 * t]);
                acc[2 * t + 1] = fma2(pp, vv.y, acc[2 * t + 1]);
            }
        }
    }

    g_pm[c][row] = mR;
    g_pl[c][row] = lR;
    // acc layout is bit-identical to float[64]
    ulonglong2* po = (ulonglong2*)g_pout[c][row];
    #pragma unroll
    for (int t = 0; t < DKE / 4; t++)
        po[t] = make_ulonglong2(acc[2 * t], acc[2 * t + 1]);
}

// Combine: one warp per row; lane handles dims (lane, lane+32). Coalesced.
__global__ void attn_phase2(float* __restrict__ out) {
    const int row  = blockIdx.x * 8 + (threadIdx.x >> 5);
    const int lane = threadIdx.x & 31;
    const int nch  = (row / QT) / CPT + 1;

    float gmax = -1e30f;
    #pragma unroll
    for (int c = 0; c < MAXC; c++)
        if (c < nch) gmax = fmaxf(gmax, g_pm[c][row]);

    float denom = 0.f, o0 = 0.f, o1 = 0.f;
    for (int c = 0; c < nch; c++) {
        float w = __expf(g_pm[c][row] - gmax);
        denom = fmaf(w, g_pl[c][row], denom);
        o0 = fmaf(w, g_pout[c][row][lane],      o0);
        o1 = fmaf(w, g_pout[c][row][lane + 32], o1);
    }
    float inv = 1.0f / denom;
    out[(size_t)row * DKE + lane]      = o0 * inv;
    out[(size_t)row * DKE + lane + 32] = o1 * inv;
}

extern "C" void kernel_launch(void* const* d_in, const int* in_sizes, int n_in,
                              void* d_out, int out_size) {
    const float* q = (const float*)d_in[0];
    const float* k = (const float*)d_in[1];
    const float* v = (const float*)d_in[2];
    float* out = (float*)d_out;

    dim3 grid1(MAXC, NQT);             // 8 x 64; inactive (c,m) pairs exit fast
    attn_phase1<<<grid1, QT>>>(q, k, v);
    attn_phase2<<<SEQ / 8, 256>>>(out);
}

// round 3
// speedup vs baseline: 4.0981x; 3.8148x over previous
#include <cuda_runtime.h>
#include <stdint.h>

#define SEQ   8192
#define DKE   64
#define QT    128          // query rows per CTA
#define KT    64           // keys per smem tile
#define CHUNK 1024         // keys per split-K chunk
#define NQT   (SEQ/QT)     // 64
#define MAXC  (SEQ/CHUNK)  // 8
#define CPT   (CHUNK/QT)   // 8
#define NWARP 8
#define WROWS 16           // q rows per warp

#define KS_STRIDE 68       // words; bank(4g+t) = lane -> conflict-free K B-frags
#define VS_STRIDE 72       // words; bank(8t+g) = lane -> conflict-free V B-frags

// Split-K partials (scratch via __device__ globals; no allocation)
__device__ float g_pout[MAXC][SEQ][DKE];
__device__ float g_pm[MAXC][SEQ];
__device__ float g_pl[MAXC][SEQ];

__device__ __forceinline__ uint32_t f2tf32(float x) {
    uint32_t r;
    asm("cvt.rna.tf32.f32 %0, %1;" : "=r"(r) : "f"(x));
    return r;
}

__device__ __forceinline__ void mma_tf32(float c[4], const uint32_t a[4],
                                         uint32_t b0, uint32_t b1) {
    asm("mma.sync.aligned.m16n8k8.row.col.f32.tf32.tf32.f32 "
        "{%0,%1,%2,%3}, {%4,%5,%6,%7}, {%8,%9}, {%0,%1,%2,%3};"
        : "+f"(c[0]), "+f"(c[1]), "+f"(c[2]), "+f"(c[3])
        : "r"(a[0]), "r"(a[1]), "r"(a[2]), "r"(a[3]), "r"(b0), "r"(b1));
}

__global__ __launch_bounds__(256, 2)
void attn_phase1(const float* __restrict__ q,
                 const float* __restrict__ k,
                 const float* __restrict__ v) {
    const int m = blockIdx.y;
    const int c = blockIdx.x;
    if (c > m / CPT) return;

    __shared__ uint32_t ks[KT][KS_STRIDE];   // tf32 bits
    __shared__ uint32_t vs[KT][VS_STRIDE];   // tf32 bits

    const int tid  = threadIdx.x;
    const int w    = tid >> 5;
    const int lane = tid & 31;
    const int g    = lane >> 2;      // row group 0..7
    const int t    = lane & 3;       // thread-in-quad
    const int row_base = m * QT + w * WROWS;
    const int row0 = row_base + g;
    const int row1 = row0 + 8;

    // ---- Q fragments in registers, pre-scaled by 1/64 (exact), tf32-rounded ----
    uint32_t qA[8][4];
    #pragma unroll
    for (int ka = 0; ka < 8; ka++) {
        qA[ka][0] = f2tf32(q[(size_t)row0 * DKE + ka * 8 + t]     * (1.f / 64.f));
        qA[ka][1] = f2tf32(q[(size_t)row1 * DKE + ka * 8 + t]     * (1.f / 64.f));
        qA[ka][2] = f2tf32(q[(size_t)row0 * DKE + ka * 8 + t + 4] * (1.f / 64.f));
        qA[ka][3] = f2tf32(q[(size_t)row1 * DKE + ka * 8 + t + 4] * (1.f / 64.f));
    }

    float o[8][4];
    #pragma unroll
    for (int nb = 0; nb < 8; nb++)
        o[nb][0] = o[nb][1] = o[nb][2] = o[nb][3] = 0.f;
    float m0 = -1e30f, m1 = -1e30f, l0 = 0.f, l1 = 0.f;

    const int kstart = c * CHUNK;
    const int kend   = min(kstart + CHUNK, (m + 1) * QT);
    const int src1   = (lane & ~3) | (t >> 1);   // P C->A shuffle source
    const int src2   = src1 + 2;
    const bool todd  = (t & 1);

    for (int kt = kstart; kt < kend; kt += KT) {
        __syncthreads();
        // ---- cooperative K/V tile load: fp32 -> tf32 bits into padded smem ----
        {
            const float4* kg = (const float4*)(k + (size_t)kt * DKE);
            const float4* vg = (const float4*)(v + (size_t)kt * DKE);
            #pragma unroll
            for (int i = 0; i < 4; i++) {
                int idx = tid + i * 256;          // float4 index 0..1023
                int r   = idx >> 4;
                int c4  = (idx & 15) << 2;
                float4 x = kg[idx];
                uint4 xb = make_uint4(f2tf32(x.x), f2tf32(x.y), f2tf32(x.z), f2tf32(x.w));
                *(uint4*)&ks[r][c4] = xb;
                float4 y = vg[idx];
                uint4 yb = make_uint4(f2tf32(y.x), f2tf32(y.y), f2tf32(y.z), f2tf32(y.w));
                *(uint4*)&vs[r][c4] = yb;
            }
        }
        __syncthreads();

        if (kt > row_base + WROWS - 1) continue;   // tile fully masked for this warp

        // ---- S = Q K^T (scores already scaled by 1/64 via Q) ----
        float s[8][4];
        #pragma unroll
        for (int nb = 0; nb < 8; nb++)
            s[nb][0] = s[nb][1] = s[nb][2] = s[nb][3] = 0.f;
        #pragma unroll
        for (int nb = 0; nb < 8; nb++) {
            #pragma unroll
            for (int ka = 0; ka < 8; ka++) {
                uint32_t b0 = ks[nb * 8 + g][ka * 8 + t];
                uint32_t b1 = ks[nb * 8 + g][ka * 8 + t + 4];
                mma_tf32(s[nb], qA[ka], b0, b1);
            }
        }

        // ---- causal mask ----
        if (kt + KT - 1 > row_base) {
            #pragma unroll
            for (int nb = 0; nb < 8; nb++) {
                int j0 = kt + nb * 8 + 2 * t;
                int j1 = j0 + 1;
                if (j0 > row0) s[nb][0] = -1e30f;
                if (j1 > row0) s[nb][1] = -1e30f;
                if (j0 > row1) s[nb][2] = -1e30f;
                if (j1 > row1) s[nb][3] = -1e30f;
            }
        }

        // ---- online softmax ----
        float mx0 = m0, mx1 = m1;
        #pragma unroll
        for (int nb = 0; nb < 8; nb++) {
            mx0 = fmaxf(mx0, fmaxf(s[nb][0], s[nb][1]));
            mx1 = fmaxf(mx1, fmaxf(s[nb][2], s[nb][3]));
        }
        mx0 = fmaxf(mx0, __shfl_xor_sync(0xffffffffu, mx0, 1));
        mx0 = fmaxf(mx0, __shfl_xor_sync(0xffffffffu, mx0, 2));
        mx1 = fmaxf(mx1, __shfl_xor_sync(0xffffffffu, mx1, 1));
        mx1 = fmaxf(mx1, __shfl_xor_sync(0xffffffffu, mx1, 2));

        float sc0 = __expf(m0 - mx0);
        float sc1 = __expf(m1 - mx1);
        m0 = mx0; m1 = mx1;
        #pragma unroll
        for (int nb = 0; nb < 8; nb++) {
            o[nb][0] *= sc0; o[nb][1] *= sc0;
            o[nb][2] *= sc1; o[nb][3] *= sc1;
        }

        float ps0 = 0.f, ps1 = 0.f;
        #pragma unroll
        for (int nb = 0; nb < 8; nb++) {
            s[nb][0] = __expf(s[nb][0] - m0);
            s[nb][1] = __expf(s[nb][1] - m0);
            s[nb][2] = __expf(s[nb][2] - m1);
            s[nb][3] = __expf(s[nb][3] - m1);
            ps0 += s[nb][0] + s[nb][1];
            ps1 += s[nb][2] + s[nb][3];
        }
        ps0 += __shfl_xor_sync(0xffffffffu, ps0, 1);
        ps0 += __shfl_xor_sync(0xffffffffu, ps0, 2);
        ps1 += __shfl_xor_sync(0xffffffffu, ps1, 1);
        ps1 += __shfl_xor_sync(0xffffffffu, ps1, 2);
        l0 = l0 * sc0 + ps0;
        l1 = l1 * sc1 + ps1;

        // ---- O += P V : convert C-frag -> A-frag via shuffles, then mma ----
        #pragma unroll
        for (int ksq = 0; ksq < 8; ksq++) {
            float v00 = __shfl_sync(0xffffffffu, s[ksq][0], src1);
            float v01 = __shfl_sync(0xffffffffu, s[ksq][1], src1);
            float v02 = __shfl_sync(0xffffffffu, s[ksq][0], src2);
            float v03 = __shfl_sync(0xffffffffu, s[ksq][1], src2);
            float v10 = __shfl_sync(0xffffffffu, s[ksq][2], src1);
            float v11 = __shfl_sync(0xffffffffu, s[ksq][3], src1);
            float v12 = __shfl_sync(0xffffffffu, s[ksq][2], src2);
            float v13 = __shfl_sync(0xffffffffu, s[ksq][3], src2);
            uint32_t pA[4];
            pA[0] = f2tf32(todd ? v01 : v00);
            pA[1] = f2tf32(todd ? v11 : v10);
            pA[2] = f2tf32(todd ? v03 : v02);
            pA[3] = f2tf32(todd ? v13 : v12);
            #pragma unroll
            for (int nb = 0; nb < 8; nb++) {
                uint32_t b0 = vs[ksq * 8 + t][nb * 8 + g];
                uint32_t b1 = vs[ksq * 8 + t + 4][nb * 8 + g];
                mma_tf32(o[nb], pA, b0, b1);
            }
        }
    }

    // ---- write split-K partials ----
    #pragma unroll
    for (int nb = 0; nb < 8; nb++) {
        *(float2*)&g_pout[c][row0][nb * 8 + 2 * t] = make_float2(o[nb][0], o[nb][1]);
        *(float2*)&g_pout[c][row1][nb * 8 + 2 * t] = make_float2(o[nb][2], o[nb][3]);
    }
    if (t == 0) {
        g_pm[c][row0] = m0; g_pl[c][row0] = l0;
        g_pm[c][row1] = m1; g_pl[c][row1] = l1;
    }
}

// Combine: one warp per row; lane handles dims (lane, lane+32). Coalesced.
__global__ void attn_phase2(float* __restrict__ out) {
    const int row  = blockIdx.x * 8 + (threadIdx.x >> 5);
    const int lane = threadIdx.x & 31;
    const int nch  = (row / QT) / CPT + 1;

    float gmax = -1e30f;
    #pragma unroll
    for (int c = 0; c < MAXC; c++)
        if (c < nch) gmax = fmaxf(gmax, g_pm[c][row]);

    float denom = 0.f, o0 = 0.f, o1 = 0.f;
    for (int c = 0; c < nch; c++) {
        float w = __expf(g_pm[c][row] - gmax);
        denom = fmaf(w, g_pl[c][row], denom);
        o0 = fmaf(w, g_pout[c][row][lane],      o0);
        o1 = fmaf(w, g_pout[c][row][lane + 32], o1);
    }
    float inv = 1.0f / denom;
    out[(size_t)row * DKE + lane]      = o0 * inv;
    out[(size_t)row * DKE + lane + 32] = o1 * inv;
}

extern "C" void kernel_launch(void* const* d_in, const int* in_sizes, int n_in,
                              void* d_out, int out_size) {
    const float* q = (const float*)d_in[0];
    const float* k = (const float*)d_in[1];
    const float* v = (const float*)d_in[2];
    float* out = (float*)d_out;

    dim3 grid1(MAXC, NQT);
    attn_phase1<<<grid1, 256>>>(q, k, v);
    attn_phase2<<<SEQ / 8, 256>>>(out);
}

// round 4
// speedup vs baseline: 4.4051x; 1.0749x over previous
#include <cuda_runtime.h>
#include <stdint.h>

#define SEQ   8192
#define DKE   64
#define QT    128          // query rows per CTA
#define KT    64           // keys per smem tile
#define CHUNK 1024         // keys per split-K chunk
#define NQT   (SEQ/QT)     // 64
#define MAXC  (SEQ/CHUNK)  // 8
#define CPT   (CHUNK/QT)   // 8
#define WROWS 16           // q rows per warp

// Split-K partials (scratch via __device__ globals; no allocation)
__device__ float g_pout[MAXC][SEQ][DKE];
__device__ float g_pm[MAXC][SEQ];      // row max, in log2 domain
__device__ float g_pl[MAXC][SEQ];

__device__ __forceinline__ uint32_t f2tf32(float x) {
    uint32_t r;
    asm("cvt.rna.tf32.f32 %0, %1;" : "=r"(r) : "f"(x));
    return r;
}
__device__ __forceinline__ float ex2f(float x) {
    float r;
    asm("ex2.approx.ftz.f32 %0, %1;" : "=f"(r) : "f"(x));
    return r;
}
__device__ __forceinline__ void mma_tf32(float c[4], const uint32_t a[4],
                                         uint32_t b0, uint32_t b1) {
    asm("mma.sync.aligned.m16n8k8.row.col.f32.tf32.tf32.f32 "
        "{%0,%1,%2,%3}, {%4,%5,%6,%7}, {%8,%9}, {%0,%1,%2,%3};"
        : "+f"(c[0]), "+f"(c[1]), "+f"(c[2]), "+f"(c[3])
        : "r"(a[0]), "r"(a[1]), "r"(a[2]), "r"(a[3]), "r"(b0), "r"(b1));
}

// Q prescale: 1/64 (problem's scale) * log2(e) (exp -> ex2 domain)
#define QSCALE (0.015625f * 1.44269504088896340736f)

__global__ __launch_bounds__(256, 2)
void attn_phase1(const float* __restrict__ q,
                 const float* __restrict__ k,
                 const float* __restrict__ v) {
    const int m = blockIdx.y;
    const int c = blockIdx.x;
    if (c > m / CPT) return;

    // Fragment-major tf32 tiles: one LDS.128 = one full B-fragment pair.
    // ksf[nb][kap][lane^kap][e] : e = (ka&1)*2 + hi, b0/b1 for ka=2kap,2kap+1
    // vsf[ksq][nbp][xlane][e]   : e = (nb&1)*2 + hi, b0/b1 for nb=2nbp,2nbp+1
    __shared__ uint32_t ksf[8][4][32][4];
    __shared__ uint32_t vsf[8][4][32][4];

    const int tid  = threadIdx.x;
    const int w    = tid >> 5;
    const int lane = tid & 31;
    const int g    = lane >> 2;
    const int t    = lane & 3;
    const int row_base = m * QT + w * WROWS;
    const int row0 = row_base + g;
    const int row1 = row0 + 8;

    // V-side compute swizzle (per nbp), K-side is lane^kap
    int xlv[4];
    #pragma unroll
    for (int nbp = 0; nbp < 4; nbp++)
        xlv[nbp] = (lane ^ nbp) ^ ((lane & 16) >> 2);

    // ---- Q fragments in registers (prescaled, tf32) ----
    uint32_t qA[8][4];
    #pragma unroll
    for (int ka = 0; ka < 8; ka++) {
        qA[ka][0] = f2tf32(q[(size_t)row0 * DKE + ka * 8 + t]     * QSCALE);
        qA[ka][1] = f2tf32(q[(size_t)row1 * DKE + ka * 8 + t]     * QSCALE);
        qA[ka][2] = f2tf32(q[(size_t)row0 * DKE + ka * 8 + t + 4] * QSCALE);
        qA[ka][3] = f2tf32(q[(size_t)row1 * DKE + ka * 8 + t + 4] * QSCALE);
    }

    float o[8][4];
    #pragma unroll
    for (int nb = 0; nb < 8; nb++)
        o[nb][0] = o[nb][1] = o[nb][2] = o[nb][3] = 0.f;
    float m0 = -1e30f, m1 = -1e30f, l0 = 0.f, l1 = 0.f;

    const int kstart = c * CHUNK;
    const int kend   = min(kstart + CHUNK, (m + 1) * QT);
    const int src1   = (lane & ~3) | (t >> 1);
    const int src2   = src1 + 2;
    const bool todd  = (t & 1);

    for (int kt = kstart; kt < kend; kt += KT) {
        __syncthreads();
        // ---- cooperative K/V load: fp32 -> tf32, scattered into fragment order ----
        {
            const float4* kg = (const float4*)(k + (size_t)kt * DKE);
            const float4* vg = (const float4*)(v + (size_t)kt * DKE);
            #pragma unroll
            for (int i = 0; i < 4; i++) {
                int idx = tid + i * 256;          // float4 index 0..1023
                int r   = idx >> 4;
                int c0  = (idx & 15) << 2;

                // K element (key=r, dim=c): nb=r>>3, g=r&7; ka=c>>3, t=c&3, hi=(c>>2)&1
                {
                    float4 x = kg[idx];
                    int nb  = r >> 3, gg = r & 7;
                    int ka  = c0 >> 3, kap = ka >> 1;
                    int hi  = (c0 >> 2) & 1;
                    int e   = (ka & 1) * 2 + hi;
                    uint32_t* base = &ksf[nb][kap][0][0];
                    base[((gg * 4 + (0 ^ kap)) << 2) + e] = f2tf32(x.x);
                    base[((gg * 4 + (1 ^ kap)) << 2) + e] = f2tf32(x.y);
                    base[((gg * 4 + (2 ^ kap)) << 2) + e] = f2tf32(x.z);
                    base[((gg * 4 + (3 ^ kap)) << 2) + e] = f2tf32(x.w);
                }
                // V element (key=r, dim=c): ksq=r>>3, t=r&3, hi=(r>>2)&1; nb=c>>3, g=c&7
                {
                    float4 y = vg[idx];
                    int ksq = r >> 3, tt = r & 3;
                    int hi  = (r >> 2) & 1;
                    int nb  = c0 >> 3, nbp = nb >> 1;
                    int e   = (nb & 1) * 2 + hi;
                    int g0  = c0 & 7;
                    uint32_t* base = &vsf[ksq][nbp][0][0];
                    #pragma unroll
                    for (int j = 0; j < 4; j++) {
                        int z  = (g0 + j) * 4 + tt;
                        int xl = (z ^ nbp) ^ ((z & 16) >> 2);
                        float val = (j == 0) ? y.x : (j == 1) ? y.y : (j == 2) ? y.z : y.w;
                        base[(xl << 2) + e] = f2tf32(val);
                    }
                }
            }
        }
        __syncthreads();

        if (kt > row_base + WROWS - 1) continue;

        // ---- S = Q K^T (scaled + log2 domain via Q prescale) ----
        float s[8][4];
        #pragma unroll
        for (int nb = 0; nb < 8; nb++)
            s[nb][0] = s[nb][1] = s[nb][2] = s[nb][3] = 0.f;
        #pragma unroll
        for (int nb = 0; nb < 8; nb++) {
            #pragma unroll
            for (int kap = 0; kap < 4; kap++) {
                uint4 b = *(const uint4*)&ksf[nb][kap][lane ^ kap][0];
                mma_tf32(s[nb], qA[2 * kap],     b.x, b.y);
                mma_tf32(s[nb], qA[2 * kap + 1], b.z, b.w);
            }
        }

        // ---- causal mask ----
        if (kt + KT - 1 > row_base) {
            #pragma unroll
            for (int nb = 0; nb < 8; nb++) {
                int j0 = kt + nb * 8 + 2 * t;
                int j1 = j0 + 1;
                if (j0 > row0) s[nb][0] = -1e30f;
                if (j1 > row0) s[nb][1] = -1e30f;
                if (j0 > row1) s[nb][2] = -1e30f;
                if (j1 > row1) s[nb][3] = -1e30f;
            }
        }

        // ---- online softmax (log2 domain) ----
        float mx0 = m0, mx1 = m1;
        #pragma unroll
        for (int nb = 0; nb < 8; nb++) {
            mx0 = fmaxf(mx0, fmaxf(s[nb][0], s[nb][1]));
            mx1 = fmaxf(mx1, fmaxf(s[nb][2], s[nb][3]));
        }
        mx0 = fmaxf(mx0, __shfl_xor_sync(0xffffffffu, mx0, 1));
        mx0 = fmaxf(mx0, __shfl_xor_sync(0xffffffffu, mx0, 2));
        mx1 = fmaxf(mx1, __shfl_xor_sync(0xffffffffu, mx1, 1));
        mx1 = fmaxf(mx1, __shfl_xor_sync(0xffffffffu, mx1, 2));

        float sc0 = ex2f(m0 - mx0);
        float sc1 = ex2f(m1 - mx1);
        m0 = mx0; m1 = mx1;
        #pragma unroll
        for (int nb = 0; nb < 8; nb++) {
            o[nb][0] *= sc0; o[nb][1] *= sc0;
            o[nb][2] *= sc1; o[nb][3] *= sc1;
        }

        float ps0 = 0.f, ps1 = 0.f;
        #pragma unroll
        for (int nb = 0; nb < 8; nb++) {
            s[nb][0] = ex2f(s[nb][0] - m0);
            s[nb][1] = ex2f(s[nb][1] - m0);
            s[nb][2] = ex2f(s[nb][2] - m1);
            s[nb][3] = ex2f(s[nb][3] - m1);
            ps0 += s[nb][0] + s[nb][1];
            ps1 += s[nb][2] + s[nb][3];
        }
        ps0 += __shfl_xor_sync(0xffffffffu, ps0, 1);
        ps0 += __shfl_xor_sync(0xffffffffu, ps0, 2);
        ps1 += __shfl_xor_sync(0xffffffffu, ps1, 1);
        ps1 += __shfl_xor_sync(0xffffffffu, ps1, 2);
        l0 = l0 * sc0 + ps0;
        l1 = l1 * sc1 + ps1;

        // ---- O += P V ----
        #pragma unroll
        for (int ksq = 0; ksq < 8; ksq++) {
            float v00 = __shfl_sync(0xffffffffu, s[ksq][0], src1);
            float v01 = __shfl_sync(0xffffffffu, s[ksq][1], src1);
            float v02 = __shfl_sync(0xffffffffu, s[ksq][0], src2);
            float v03 = __shfl_sync(0xffffffffu, s[ksq][1], src2);
            float v10 = __shfl_sync(0xffffffffu, s[ksq][2], src1);
            float v11 = __shfl_sync(0xffffffffu, s[ksq][3], src1);
            float v12 = __shfl_sync(0xffffffffu, s[ksq][2], src2);
            float v13 = __shfl_sync(0xffffffffu, s[ksq][3], src2);
            uint32_t pA[4];
            pA[0] = f2tf32(todd ? v01 : v00);
            pA[1] = f2tf32(todd ? v11 : v10);
            pA[2] = f2tf32(todd ? v03 : v02);
            pA[3] = f2tf32(todd ? v13 : v12);
            #pragma unroll
            for (int nbp = 0; nbp < 4; nbp++) {
                uint4 b = *(const uint4*)&vsf[ksq][nbp][xlv[nbp]][0];
                mma_tf32(o[2 * nbp],     pA, b.x, b.y);
                mma_tf32(o[2 * nbp + 1], pA, b.z, b.w);
            }
        }
    }

    // ---- write split-K partials ----
    #pragma unroll
    for (int nb = 0; nb < 8; nb++) {
        *(float2*)&g_pout[c][row0][nb * 8 + 2 * t] = make_float2(o[nb][0], o[nb][1]);
        *(float2*)&g_pout[c][row1][nb * 8 + 2 * t] = make_float2(o[nb][2], o[nb][3]);
    }
    if (t == 0) {
        g_pm[c][row0] = m0; g_pl[c][row0] = l0;
        g_pm[c][row1] = m1; g_pl[c][row1] = l1;
    }
}

// Combine: one warp per row; lane handles dims (lane, lane+32). Coalesced.
__global__ void attn_phase2(float* __restrict__ out) {
    const int row  = blockIdx.x * 8 + (threadIdx.x >> 5);
    const int lane = threadIdx.x & 31;
    const int nch  = (row / QT) / CPT + 1;

    float gmax = -1e30f;
    #pragma unroll
    for (int c = 0; c < MAXC; c++)
        if (c < nch) gmax = fmaxf(gmax, g_pm[c][row]);

    float denom = 0.f, o0 = 0.f, o1 = 0.f;
    for (int c = 0; c < nch; c++) {
        float w = ex2f(g_pm[c][row] - gmax);   // log2-domain partials
        denom = fmaf(w, g_pl[c][row], denom);
        o0 = fmaf(w, g_pout[c][row][lane],      o0);
        o1 = fmaf(w, g_pout[c][row][lane + 32], o1);
    }
    float inv = 1.0f / denom;
    out[(size_t)row * DKE + lane]      = o0 * inv;
    out[(size_t)row * DKE + lane + 32] = o1 * inv;
}

extern "C" void kernel_launch(void* const* d_in, const int* in_sizes, int n_in,
                              void* d_out, int out_size) {
    const float* q = (const float*)d_in[0];
    const float* k = (const float*)d_in[1];
    const float* v = (const float*)d_in[2];
    float* out = (float*)d_out;

    dim3 grid1(MAXC, NQT);
    attn_phase1<<<grid1, 256>>>(q, k, v);
    attn_phase2<<<SEQ / 8, 256>>>(out);
}